// round 16
// baseline (speedup 1.0000x reference)
#include <cuda_runtime.h>

#define NN   50000
#define EE   800000
#define FIN  64
#define HID  128
#define NCLS 10
#define NG   128
#define KTOP 400000
#define MAX_TIES 4096
#define TKB  592              // topk persistent grid (148 SM x 4)

struct SelState {
    unsigned prefix;
    int kk;
    unsigned threshold;
    int needed;
    int tie_count;
};

struct __align__(16) Scratch {
    float h [(size_t)NN * HID];
    float Ai[(size_t)NN * HID];
    float At[(size_t)NN * HID];
    float Ar[(size_t)NN * HID];
    float T1[(size_t)NN * HID];
    float T2[(size_t)NN * HID];
    float X1[(size_t)NN * HID];
    float X2[(size_t)NN * HID];
    float ew[EE];
    unsigned hist[2048];
    int tie[MAX_TIES];
    float pool[NG * HID];
    int deg[NN];
    int off[NN + 1];
    int cursor[NN];
    int2 pack[EE];            // (eid, src_row) per CSR slot
    int bar_cnt;
    int bar_gen;
    SelState st;
};
__device__ Scratch g_s;

// ---------------------------------------------------------------------------
// helpers
// ---------------------------------------------------------------------------
__device__ __forceinline__ void red4(float* addr, float4 v) {
    asm volatile("red.global.add.v4.f32 [%0], {%1,%2,%3,%4};"
                 :: "l"(addr), "f"(v.x), "f"(v.y), "f"(v.z), "f"(v.w)
                 : "memory");
}

__device__ __forceinline__ unsigned fkey(float f) {
    unsigned u = __float_as_uint(f);
    return (u & 0x80000000u) ? ~u : (u | 0x80000000u);
}

// packed fp32x2 FMA (Blackwell): d = a * b + d
__device__ __forceinline__ void ffma2(unsigned long long& d,
                                      unsigned long long a,
                                      unsigned long long b) {
    asm("fma.rn.f32x2 %0, %1, %2, %0;" : "+l"(d) : "l"(a), "l"(b));
}

__device__ __forceinline__ unsigned long long dup2(float a) {
    unsigned long long r;
    asm("mov.b64 %0, {%1, %1};" : "=l"(r) : "r"(__float_as_uint(a)));
    return r;
}

__device__ __forceinline__ float2 unpk(unsigned long long v) {
    float2 r;
    asm("mov.b64 {%0, %1}, %2;" : "=f"(r.x), "=f"(r.y) : "l"(v));
    return r;
}

// software grid barrier (all TKB blocks resident by construction)
__device__ __forceinline__ void gbar(int* cnt, volatile int* gen, int nblk) {
    __syncthreads();
    if (threadIdx.x == 0) {
        int g = *gen;
        __threadfence();
        int v = atomicAdd(cnt, 1);
        if (v == nblk - 1) {
            *cnt = 0;
            __threadfence();
            *gen = g + 1;
        } else {
            while (*gen == g) { }
        }
    }
    __syncthreads();
}

// ---------------------------------------------------------------------------
// zero / init
// ---------------------------------------------------------------------------
__global__ void zero_init(Scratch* s) {
    int idx = blockIdx.x * blockDim.x + threadIdx.x;
    int stride = gridDim.x * blockDim.x;
    for (int i = idx; i < NN; i += stride) s->deg[i] = 0;
    if (idx < (int)(NG * HID / 4)) ((float4*)s->pool)[idx] =
        make_float4(0.f, 0.f, 0.f, 0.f);
    if (idx < 2048) s->hist[idx] = 0;
    if (idx == 0) {
        s->st.prefix = 0;
        s->st.kk = KTOP;
        s->st.tie_count = 0;
        s->bar_cnt = 0;
        s->bar_gen = 0;
    }
}

// ---------------------------------------------------------------------------
// CSR-by-destination build: count -> scan (warp-shuffle) -> fill (packed)
// ---------------------------------------------------------------------------
__global__ void count_deg(const int* __restrict__ col, int* __restrict__ deg) {
    int t = blockIdx.x * 256 + threadIdx.x;
    int e0 = t * 4;
    if (e0 >= EE) return;
    int4 c = *(const int4*)&col[e0];
    atomicAdd(&deg[c.x], 1);
    atomicAdd(&deg[c.y], 1);
    atomicAdd(&deg[c.z], 1);
    atomicAdd(&deg[c.w], 1);
}

__global__ void scan_deg(const int* __restrict__ deg, int* __restrict__ off,
                         int* __restrict__ cursor) {
    __shared__ int wsum[32];
    __shared__ int carry_s;
    int tid = threadIdx.x;               // 1024 threads
    int lane = tid & 31, wid = tid >> 5;
    if (tid == 0) carry_s = 0;
    __syncthreads();
    for (int base = 0; base < NN; base += 1024) {
        int i = base + tid;
        int v = (i < NN) ? deg[i] : 0;
        int x = v;
#pragma unroll
        for (int o = 1; o < 32; o <<= 1) {
            int t = __shfl_up_sync(0xFFFFFFFFu, x, o);
            if (lane >= o) x += t;
        }
        if (lane == 31) wsum[wid] = x;
        __syncthreads();
        if (wid == 0) {
            int w = wsum[lane];
#pragma unroll
            for (int o = 1; o < 32; o <<= 1) {
                int t = __shfl_up_sync(0xFFFFFFFFu, w, o);
                if (lane >= o) w += t;
            }
            wsum[lane] = w;
        }
        __syncthreads();
        int excl = x - v + (wid > 0 ? wsum[wid - 1] : 0) + carry_s;
        if (i < NN) { off[i] = excl; cursor[i] = excl; }
        __syncthreads();
        if (tid == 1023) carry_s = excl + v;
        __syncthreads();
    }
    if (tid == 0) off[NN] = carry_s;
}

__global__ void fill_eid(const int* __restrict__ row, const int* __restrict__ col,
                         int* __restrict__ cursor, int2* __restrict__ pack) {
    int t = blockIdx.x * 256 + threadIdx.x;
    int e0 = t * 4;
    if (e0 >= EE) return;
    int4 c = *(const int4*)&col[e0];
    int4 r = *(const int4*)&row[e0];
    int p0 = atomicAdd(&cursor[c.x], 1);
    int p1 = atomicAdd(&cursor[c.y], 1);
    int p2 = atomicAdd(&cursor[c.z], 1);
    int p3 = atomicAdd(&cursor[c.w], 1);
    pack[p0] = make_int2(e0 + 0, r.x);
    pack[p1] = make_int2(e0 + 1, r.y);
    pack[p2] = make_int2(e0 + 2, r.z);
    pack[p3] = make_int2(e0 + 3, r.w);
}

// ---------------------------------------------------------------------------
// GEMM: C[M x 128] = epilogue( (A + optional 2*H)[M x K] @ W[K x 128] + bias )
// Block tile 64 x 128, BK=16, 128 threads, 8x8 microtile, FFMA2 inner product.
// ---------------------------------------------------------------------------
struct GArgs {
    const float* A;
    const float* W;
    const float* bias;
    float* C;
};

template<int K, bool ADD2H, bool RELU>
__global__ __launch_bounds__(128, 4)
void gemm64(GArgs g0, GArgs g1, const float* __restrict__ Hh, int M)
{
    __shared__ __align__(16) float As[2][16][64];
    __shared__ __align__(16) float Bs[2][16][128];

    GArgs g = (blockIdx.y == 1) ? g1 : g0;
    const float* __restrict__ A = g.A;
    const float* __restrict__ W = g.W;

    const int m0 = blockIdx.x * 64;
    const int t  = threadIdx.x;
    const int tx = t & 15;
    const int ty = t >> 4;

    const int ar0 = t >> 2;
    const int akc = (t & 3) * 4;
    const int bkr = t >> 5;
    const int bc4 = (t & 31) * 4;

    unsigned long long acc2[8][4];
#pragma unroll
    for (int i = 0; i < 8; i++)
#pragma unroll
        for (int j = 0; j < 4; j++) acc2[i][j] = 0ull;

    float4 av[2], bv[4];

    auto ldg_tiles = [&](int k0) {
#pragma unroll
        for (int l = 0; l < 2; l++) {
            int m = m0 + ar0 + l * 32;
            float4 v = make_float4(0.f, 0.f, 0.f, 0.f);
            if (m < M) {
                v = *(const float4*)&A[(size_t)m * K + k0 + akc];
                if (ADD2H) {
                    float4 hv = *(const float4*)&Hh[(size_t)m * K + k0 + akc];
                    v.x += 2.f * hv.x; v.y += 2.f * hv.y;
                    v.z += 2.f * hv.z; v.w += 2.f * hv.w;
                }
            }
            av[l] = v;
        }
#pragma unroll
        for (int l = 0; l < 4; l++)
            bv[l] = *(const float4*)&W[(size_t)(k0 + bkr + l * 4) * 128 + bc4];
    };

    auto sts_tiles = [&](int buf) {
#pragma unroll
        for (int l = 0; l < 2; l++) {
            int r = ar0 + l * 32;
            As[buf][akc + 0][r] = av[l].x;
            As[buf][akc + 1][r] = av[l].y;
            As[buf][akc + 2][r] = av[l].z;
            As[buf][akc + 3][r] = av[l].w;
        }
#pragma unroll
        for (int l = 0; l < 4; l++)
            *(float4*)&Bs[buf][bkr + l * 4][bc4] = bv[l];
    };

    auto compute = [&](int buf) {
#pragma unroll
        for (int kk = 0; kk < 16; kk++) {
            float4 a0 = *(const float4*)&As[buf][kk][ty * 4];
            float4 a1 = *(const float4*)&As[buf][kk][32 + ty * 4];
            ulonglong2 p0 = *(const ulonglong2*)&Bs[buf][kk][tx * 4];
            ulonglong2 p1 = *(const ulonglong2*)&Bs[buf][kk][64 + tx * 4];
            unsigned long long bb[4] = {p0.x, p0.y, p1.x, p1.y};
            float aa[8] = {a0.x, a0.y, a0.z, a0.w, a1.x, a1.y, a1.z, a1.w};
#pragma unroll
            for (int i = 0; i < 8; i++) {
                unsigned long long ad = dup2(aa[i]);
                ffma2(acc2[i][0], ad, bb[0]);
                ffma2(acc2[i][1], ad, bb[1]);
                ffma2(acc2[i][2], ad, bb[2]);
                ffma2(acc2[i][3], ad, bb[3]);
            }
        }
    };

    ldg_tiles(0);
    sts_tiles(0);
    __syncthreads();
    int buf = 0;
    for (int k0 = 16; k0 < K; k0 += 16) {
        ldg_tiles(k0);
        compute(buf);
        sts_tiles(buf ^ 1);
        __syncthreads();
        buf ^= 1;
    }
    compute(buf);

    const float4 bias0 = *(const float4*)&g.bias[tx * 4];
    const float4 bias1 = *(const float4*)&g.bias[64 + tx * 4];
#pragma unroll
    for (int gi = 0; gi < 2; gi++) {
#pragma unroll
        for (int i = 0; i < 4; i++) {
            int m = m0 + gi * 32 + ty * 4 + i;
            if (m >= M) continue;
            int ri = gi * 4 + i;
            float2 c0 = unpk(acc2[ri][0]);
            float2 c1 = unpk(acc2[ri][1]);
            float2 c2 = unpk(acc2[ri][2]);
            float2 c3 = unpk(acc2[ri][3]);
            float4 v0, v1;
            v0.x = c0.x + bias0.x; v0.y = c0.y + bias0.y;
            v0.z = c1.x + bias0.z; v0.w = c1.y + bias0.w;
            v1.x = c2.x + bias1.x; v1.y = c2.y + bias1.y;
            v1.z = c3.x + bias1.z; v1.w = c3.y + bias1.w;
            if (RELU) {
                v0.x = fmaxf(v0.x, 0.f); v0.y = fmaxf(v0.y, 0.f);
                v0.z = fmaxf(v0.z, 0.f); v0.w = fmaxf(v0.w, 0.f);
                v1.x = fmaxf(v1.x, 0.f); v1.y = fmaxf(v1.y, 0.f);
                v1.z = fmaxf(v1.z, 0.f); v1.w = fmaxf(v1.w, 0.f);
            }
            *(float4*)&g.C[(size_t)m * 128 + tx * 4] = v0;
            *(float4*)&g.C[(size_t)m * 128 + 64 + tx * 4] = v1;
        }
    }
}

// ---------------------------------------------------------------------------
// gather (weight 1): Ai[n] = sum over incoming edges of h[src]
// ---------------------------------------------------------------------------
__global__ void gather_ones(const int* __restrict__ off, const int2* __restrict__ pack,
                            const float* __restrict__ h, float* __restrict__ Ai)
{
    int n = blockIdx.x * 8 + (threadIdx.x >> 5);
    if (n >= NN) return;
    int lane = threadIdx.x & 31;
    int s0 = __ldg(&off[n]);
    int cnt = __ldg(&off[n + 1]) - s0;
    float4 acc0 = make_float4(0.f, 0.f, 0.f, 0.f);
    float4 acc1 = make_float4(0.f, 0.f, 0.f, 0.f);
    for (int base = 0; base < cnt; base += 32) {
        int m = cnt - base; if (m > 32) m = 32;
        int src = 0;
        if (base + lane < cnt) src = __ldg(&pack[s0 + base + lane].y);
        int j = 0;
        for (; j + 2 <= m; j += 2) {
            int r0 = __shfl_sync(0xFFFFFFFFu, src, j);
            int r1 = __shfl_sync(0xFFFFFFFFu, src, j + 1);
            float4 v0 = *(const float4*)(h + (size_t)r0 * HID + lane * 4);
            float4 v1 = *(const float4*)(h + (size_t)r1 * HID + lane * 4);
            acc0.x += v0.x; acc0.y += v0.y; acc0.z += v0.z; acc0.w += v0.w;
            acc1.x += v1.x; acc1.y += v1.y; acc1.z += v1.z; acc1.w += v1.w;
        }
        if (j < m) {
            int r0 = __shfl_sync(0xFFFFFFFFu, src, j);
            float4 v0 = *(const float4*)(h + (size_t)r0 * HID + lane * 4);
            acc0.x += v0.x; acc0.y += v0.y; acc0.z += v0.z; acc0.w += v0.w;
        }
    }
    float4 acc = make_float4(acc0.x + acc1.x, acc0.y + acc1.y,
                             acc0.z + acc1.z, acc0.w + acc1.w);
    *(float4*)(Ai + (size_t)n * HID + lane * 4) = acc;
}

// ---------------------------------------------------------------------------
// per-edge dot: ew[e] = <X[row], X[col]> — 4 edges per warp
// ---------------------------------------------------------------------------
__global__ void ew_kernel(const int* __restrict__ row, const int* __restrict__ col,
                          const float* __restrict__ X, float* __restrict__ ew)
{
    int gw = blockIdx.x * 8 + (threadIdx.x >> 5);
    int e0 = gw * 4;
    if (e0 >= EE) return;
    int lane = threadIdx.x & 31;
    int r[4], c[4];
#pragma unroll
    for (int q = 0; q < 4; q++) {
        r[q] = __ldg(&row[e0 + q]);
        c[q] = __ldg(&col[e0 + q]);
    }
    float s[4];
#pragma unroll
    for (int q = 0; q < 4; q++) {
        float4 a = *(const float4*)(X + (size_t)r[q] * HID + lane * 4);
        float4 b = *(const float4*)(X + (size_t)c[q] * HID + lane * 4);
        s[q] = a.x * b.x + a.y * b.y + a.z * b.z + a.w * b.w;
    }
#pragma unroll
    for (int off = 16; off >= 1; off >>= 1) {
#pragma unroll
        for (int q = 0; q < 4; q++)
            s[q] += __shfl_xor_sync(0xFFFFFFFFu, s[q], off);
    }
    if (lane == 0)
        *(float4*)&ew[e0] = make_float4(s[0], s[1], s[2], s[3]);
}

// ---------------------------------------------------------------------------
// fused persistent top-k radix select: hist0->scan->hist1->scan->hist2->scan
// in ONE kernel with a software grid barrier. Grid = TKB (all resident).
// ---------------------------------------------------------------------------
__global__ __launch_bounds__(256, 4)
void topk_fused(const float* __restrict__ ew, unsigned* hist, SelState* st,
                int* bar_cnt, int* bar_gen)
{
    __shared__ unsigned sh[2048];     // privatized hist / scan buffer a
    __shared__ unsigned sb[2048];     // scan buffer b
    __shared__ int bstar;
    const int tid = threadIdx.x;
    const int gstride = TKB * 256;
    volatile int* vgen = (volatile int*)bar_gen;

    // helper: one histogram pass (pass 0/1/2)
    auto hist_pass = [&](int pass) {
        for (int i = tid; i < 2048; i += 256) sh[i] = 0;
        __syncthreads();
        unsigned pref = (pass == 0) ? 0u : *(volatile unsigned*)&st->prefix;
        for (int i = blockIdx.x * 256 + tid; i < EE / 4; i += gstride) {
            float4 w = *(const float4*)&ew[i * 4];
            unsigned u[4] = {fkey(w.x), fkey(w.y), fkey(w.z), fkey(w.w)};
#pragma unroll
            for (int q = 0; q < 4; q++) {
                if (pass == 0) {
                    atomicAdd(&sh[u[q] >> 21], 1u);
                } else if (pass == 1) {
                    if ((u[q] >> 21) == pref) atomicAdd(&sh[(u[q] >> 10) & 2047u], 1u);
                } else {
                    if ((u[q] >> 10) == pref) atomicAdd(&sh[u[q] & 1023u], 1u);
                }
            }
        }
        __syncthreads();
        for (int i = tid; i < 2048; i += 256)
            if (sh[i]) atomicAdd(&hist[i], sh[i]);
    };

    // helper: block 0 scans hist (suffix sums), selects bucket, updates st,
    // and zeroes hist for the next pass.
    auto scan_phase = [&](int nbins, int bits, int last) {
        if (blockIdx.x != 0) return;
        for (int i = tid; i < 2048; i += 256) {
            sh[i] = (i < nbins) ? *(volatile unsigned*)&hist[i] : 0u;
            hist[i] = 0u;
        }
        __syncthreads();
        unsigned* src = sh;
        unsigned* dst = sb;
        for (int off = 1; off < nbins; off <<= 1) {
            for (int i = tid; i < nbins; i += 256)
                dst[i] = src[i] + ((i + off < nbins) ? src[i + off] : 0u);
            __syncthreads();
            unsigned* t = src; src = dst; dst = t;
        }
        int kk = st->kk;
        for (int i = tid; i < nbins; i += 256) {
            unsigned Si = src[i];
            unsigned Sn = (i + 1 < nbins) ? src[i + 1] : 0u;
            if (Si >= (unsigned)kk && Sn < (unsigned)kk) bstar = i;
        }
        __syncthreads();
        if (tid == 0) {
            int bs = bstar;
            unsigned greater = (bs + 1 < nbins) ? src[bs + 1] : 0u;
            st->kk = kk - (int)greater;
            st->prefix = (st->prefix << bits) | (unsigned)bs;
            if (last) {
                st->threshold = st->prefix;
                st->needed = st->kk;
            }
        }
        __syncthreads();
    };

    hist_pass(0);
    gbar(bar_cnt, vgen, TKB);
    scan_phase(2048, 11, 0);
    gbar(bar_cnt, vgen, TKB);
    hist_pass(1);
    gbar(bar_cnt, vgen, TKB);
    scan_phase(2048, 11, 0);
    gbar(bar_cnt, vgen, TKB);
    hist_pass(2);
    gbar(bar_cnt, vgen, TKB);
    scan_phase(1024, 10, 1);
}

// ---------------------------------------------------------------------------
// weighted gather with inline classification (one warp per node, no fp atomics)
// ---------------------------------------------------------------------------
__global__ void gather_sel(const int* __restrict__ off, const int2* __restrict__ pack,
                           const float* __restrict__ h, const float* __restrict__ ew,
                           float* __restrict__ At, float* __restrict__ Ar,
                           int* __restrict__ tie, SelState* __restrict__ st)
{
    int n = blockIdx.x * 8 + (threadIdx.x >> 5);
    if (n >= NN) return;
    int lane = threadIdx.x & 31;
    unsigned T = st->threshold;
    int s0 = __ldg(&off[n]);
    int cnt = __ldg(&off[n + 1]) - s0;
    float4 at0 = make_float4(0.f, 0.f, 0.f, 0.f);
    float4 at1 = make_float4(0.f, 0.f, 0.f, 0.f);
    float4 ar0 = make_float4(0.f, 0.f, 0.f, 0.f);
    float4 ar1 = make_float4(0.f, 0.f, 0.f, 0.f);
    for (int base = 0; base < cnt; base += 32) {
        int m = cnt - base; if (m > 32) m = 32;
        int src = 0; float w = 0.f; unsigned u = 0;
        if (base + lane < cnt) {
            int2 pk = __ldg(&pack[s0 + base + lane]);
            src = pk.y;
            w = __ldg(&ew[pk.x]);
            u = fkey(w);
            if (u == T) {
                int q = atomicAdd(&st->tie_count, 1);
                if (q < MAX_TIES) tie[q] = pk.x;
            }
        }
        for (int j = 0; j < m; j++) {
            unsigned uj = __shfl_sync(0xFFFFFFFFu, u, j);
            if (uj == T) continue;
            int rj = __shfl_sync(0xFFFFFFFFu, src, j);
            float wj = __shfl_sync(0xFFFFFFFFu, w, j);
            float4 v = *(const float4*)(h + (size_t)rj * HID + lane * 4);
            v.x *= wj; v.y *= wj; v.z *= wj; v.w *= wj;
            if (uj > T) {
                if (j & 1) {
                    at1.x += v.x; at1.y += v.y; at1.z += v.z; at1.w += v.w;
                } else {
                    at0.x += v.x; at0.y += v.y; at0.z += v.z; at0.w += v.w;
                }
            } else {
                if (j & 1) {
                    ar1.x += v.x; ar1.y += v.y; ar1.z += v.z; ar1.w += v.w;
                } else {
                    ar0.x += v.x; ar0.y += v.y; ar0.z += v.z; ar0.w += v.w;
                }
            }
        }
    }
    float4 at = make_float4(at0.x + at1.x, at0.y + at1.y,
                            at0.z + at1.z, at0.w + at1.w);
    float4 ar = make_float4(ar0.x + ar1.x, ar0.y + ar1.y,
                            ar0.z + ar1.z, ar0.w + ar1.w);
    *(float4*)(At + (size_t)n * HID + lane * 4) = at;
    *(float4*)(Ar + (size_t)n * HID + lane * 4) = ar;
}

// ---------------------------------------------------------------------------
// tie resolution + tie scatter (RED onto fully-written At/Ar)
// ---------------------------------------------------------------------------
__global__ void tie_resolve(const int* __restrict__ row, const int* __restrict__ col,
                            const float* __restrict__ h, const float* __restrict__ ew,
                            int* __restrict__ tie, float* __restrict__ At,
                            float* __restrict__ Ar, const SelState* __restrict__ st)
{
    __shared__ int s[MAX_TIES];
    int C = st->tie_count;
    if (C > MAX_TIES) C = MAX_TIES;
    int nd = st->needed;
    int tid = threadIdx.x;

    for (int i = tid; i < C; i += blockDim.x) s[i] = tie[i];
    __syncthreads();
    if (C > nd) {
        for (int ph = 0; ph < C; ph++) {
            for (int i = 2 * tid + (ph & 1); i + 1 < C; i += 2 * blockDim.x) {
                if (s[i] > s[i + 1]) { int t = s[i]; s[i] = s[i + 1]; s[i + 1] = t; }
            }
            __syncthreads();
        }
    }
    int lane = tid & 31;
    for (int j = tid >> 5; j < C; j += blockDim.x >> 5) {
        int e = s[j];
        float w = __ldg(&ew[e]);
        int r = __ldg(&row[e]);
        int c = __ldg(&col[e]);
        float4 v = *(const float4*)(h + (size_t)r * HID + lane * 4);
        v.x *= w; v.y *= w; v.z *= w; v.w *= w;
        float* dst = (C <= nd || j < nd) ? At : Ar;
        red4(dst + (size_t)c * HID + lane * 4, v);
    }
}

// ---------------------------------------------------------------------------
// pooling: pooled[batch[n]] += x1[n] + x2[n]   (batch sorted -> run flush)
// ---------------------------------------------------------------------------
#define NPB 128
__global__ void pool_kernel(const float* __restrict__ x1, const float* __restrict__ x2,
                            const int* __restrict__ batch, float* __restrict__ pooled)
{
    int f = threadIdx.x;
    int n0 = blockIdx.x * NPB;
    if (n0 >= NN) return;
    int n1 = n0 + NPB;
    if (n1 > NN) n1 = NN;
    int cur = batch[n0];
    float acc = 0.f;
    for (int n = n0; n < n1; n++) {
        int b = batch[n];
        if (b != cur) {
            atomicAdd(&pooled[cur * HID + f], acc);
            acc = 0.f;
            cur = b;
        }
        acc += x1[(size_t)n * HID + f] + x2[(size_t)n * HID + f];
    }
    atomicAdd(&pooled[cur * HID + f], acc);
}

// ---------------------------------------------------------------------------
// head: p = relu(pooled@post_W+post_b); logits = p@ro_W+ro_b; log_softmax
// ---------------------------------------------------------------------------
__global__ void head_kernel(const float* __restrict__ pool,
                            const float* __restrict__ pW, const float* __restrict__ pb,
                            const float* __restrict__ rW, const float* __restrict__ rb,
                            float* __restrict__ out)
{
    __shared__ float rowv[HID], p[HID], lg[NCLS];
    int g = blockIdx.x, t = threadIdx.x;
    rowv[t] = pool[g * HID + t];
    __syncthreads();
    float s = pb[t];
#pragma unroll 8
    for (int k = 0; k < HID; k++) s += rowv[k] * pW[k * HID + t];
    p[t] = fmaxf(s, 0.f);
    __syncthreads();
    if (t < NCLS) {
        float s2 = rb[t];
#pragma unroll 8
        for (int k = 0; k < HID; k++) s2 += p[k] * rW[k * NCLS + t];
        lg[t] = s2;
    }
    __syncthreads();
    if (t == 0) {
        float mx = lg[0];
        for (int j = 1; j < NCLS; j++) mx = fmaxf(mx, lg[j]);
        float se = 0.f;
        for (int j = 0; j < NCLS; j++) se += expf(lg[j] - mx);
        float l = logf(se) + mx;
        for (int j = 0; j < NCLS; j++) out[g * NCLS + j] = lg[j] - l;
    }
}

// ---------------------------------------------------------------------------
// launch
// ---------------------------------------------------------------------------
extern "C" void kernel_launch(void* const* d_in, const int* in_sizes, int n_in,
                              void* d_out, int out_size)
{
    (void)in_sizes; (void)n_in; (void)out_size;
    const float* x     = (const float*)d_in[0];
    const int*   ei    = (const int*)d_in[1];
    const int*   row   = ei;
    const int*   col   = ei + EE;
    const int*   batch = (const int*)d_in[2];
    const float* preW  = (const float*)d_in[3];
    const float* preB  = (const float*)d_in[4];
    const int LW = 2 * HID * HID, LB = 2 * HID;   // last layer (index 2)
    const float* c1W1 = (const float*)d_in[5]  + LW;
    const float* c1b1 = (const float*)d_in[6]  + LB;
    const float* c1W2 = (const float*)d_in[7]  + LW;
    const float* c1b2 = (const float*)d_in[8]  + LB;
    const float* c3W1 = (const float*)d_in[9]  + LW;
    const float* c3b1 = (const float*)d_in[10] + LB;
    const float* c3W2 = (const float*)d_in[11] + LW;
    const float* c3b2 = (const float*)d_in[12] + LB;
    const float* c4W1 = (const float*)d_in[13] + LW;
    const float* c4b1 = (const float*)d_in[14] + LB;
    const float* c4W2 = (const float*)d_in[15] + LW;
    const float* c4b2 = (const float*)d_in[16] + LB;
    const float* postW = (const float*)d_in[17];
    const float* postB = (const float*)d_in[18];
    const float* roW   = (const float*)d_in[19];
    const float* roB   = (const float*)d_in[20];
    float* out = (float*)d_out;

    Scratch* s = nullptr;
    cudaGetSymbolAddress((void**)&s, g_s);

    const int GB = (NN + 63) / 64;           // gemm blocks (x)
    const int NB = (NN + 7) / 8;             // node-warp blocks
    const int WB = (EE / 4 + 7) / 8;         // ew warp blocks (4 edges/warp)
    const int QB = (EE / 4 + 255) / 256;     // quarter-edge thread blocks
    dim3 g1(GB, 1), g2(GB, 2);

    zero_init<<<1024, 256>>>(s);

    // CSR-by-destination build (independent of h — run early)
    count_deg<<<QB, 256>>>(col, s->deg);
    scan_deg<<<1, 1024>>>(s->deg, s->off, s->cursor);
    fill_eid<<<QB, 256>>>(row, col, s->cursor, s->pack);

    // h = x @ pre_W + pre_b
    {
        GArgs a{x, preW, preB, s->h};
        gemm64<FIN, false, false><<<g1, 128>>>(a, a, nullptr, NN);
    }

    // invariance branch (only layer 2 matters)
    gather_ones<<<NB, 256>>>(s->off, s->pack, s->h, s->Ai);
    {
        GArgs a{s->Ai, c3W1, c3b1, s->T1};
        gemm64<HID, true, true><<<g1, 128>>>(a, a, s->h, NN);
    }
    {
        GArgs a{s->T1, c3W2, c3b2, s->X1};
        gemm64<HID, false, true><<<g1, 128>>>(a, a, nullptr, NN);
    }

    // per-edge weights (4 edges per warp)
    ew_kernel<<<WB, 256>>>(row, col, s->X1, s->ew);

    // exact top-k (k = 400000): fused persistent radix select (1 launch)
    topk_fused<<<TKB, 256>>>(s->ew, s->hist, &s->st, &s->bar_cnt, &s->bar_gen);

    // weighted gather with inline classification; ties deferred
    gather_sel<<<NB, 256>>>(s->off, s->pack, s->h, s->ew,
                            s->At, s->Ar, s->tie, &s->st);
    tie_resolve<<<1, 1024>>>(row, col, s->h, s->ew, s->tie, s->At, s->Ar, &s->st);

    // dual-branch layer 1: T1 = relu((At+2h)@c1W1+b), T2 = relu((Ar+2h)@c4W1+b)
    {
        GArgs a{s->At, c1W1, c1b1, s->T1};
        GArgs b{s->Ar, c4W1, c4b1, s->T2};
        gemm64<HID, true, true><<<g2, 128>>>(a, b, s->h, NN);
    }
    // dual-branch layer 2: X1 = relu(T1@c1W2+b), X2 = relu(T2@c4W2+b)
    {
        GArgs a{s->T1, c1W2, c1b2, s->X1};
        GArgs b{s->T2, c4W2, c4b2, s->X2};
        gemm64<HID, false, true><<<g2, 128>>>(a, b, nullptr, NN);
    }

    // pool + head
    pool_kernel<<<(NN + NPB - 1) / NPB, HID>>>(s->X1, s->X2, batch, s->pool);
    head_kernel<<<NG, HID>>>(s->pool, postW, postB, roW, roB, out);
}

// round 17
// speedup vs baseline: 1.0666x; 1.0666x over previous
#include <cuda_runtime.h>

#define NN   50000
#define EE   800000
#define FIN  64
#define HID  128
#define NCLS 10
#define NG   128
#define KTOP 400000
#define MAX_TIES 4096

struct SelState {
    unsigned prefix;
    int kk;
    unsigned threshold;
    int needed;
    int tie_count;
};

struct __align__(16) Scratch {
    float h [(size_t)NN * HID];
    float Ai[(size_t)NN * HID];
    float At[(size_t)NN * HID];
    float Ar[(size_t)NN * HID];
    float T1[(size_t)NN * HID];
    float T2[(size_t)NN * HID];
    float X1[(size_t)NN * HID];
    float X2[(size_t)NN * HID];
    float ew[EE];
    unsigned hist[2048];
    int tie[MAX_TIES];
    float pool[NG * HID];
    int deg[NN];
    int off[NN + 1];
    int cursor[NN];
    int2 pack[EE];            // (eid, src_row) per CSR slot
    SelState st;
};
__device__ Scratch g_s;

// ---------------------------------------------------------------------------
// helpers
// ---------------------------------------------------------------------------
__device__ __forceinline__ void red4(float* addr, float4 v) {
    asm volatile("red.global.add.v4.f32 [%0], {%1,%2,%3,%4};"
                 :: "l"(addr), "f"(v.x), "f"(v.y), "f"(v.z), "f"(v.w)
                 : "memory");
}

__device__ __forceinline__ unsigned fkey(float f) {
    unsigned u = __float_as_uint(f);
    return (u & 0x80000000u) ? ~u : (u | 0x80000000u);
}

// packed fp32x2 FMA (Blackwell): d = a * b + d
__device__ __forceinline__ void ffma2(unsigned long long& d,
                                      unsigned long long a,
                                      unsigned long long b) {
    asm("fma.rn.f32x2 %0, %1, %2, %0;" : "+l"(d) : "l"(a), "l"(b));
}

__device__ __forceinline__ unsigned long long dup2(float a) {
    unsigned long long r;
    asm("mov.b64 %0, {%1, %1};" : "=l"(r) : "r"(__float_as_uint(a)));
    return r;
}

__device__ __forceinline__ float2 unpk(unsigned long long v) {
    float2 r;
    asm("mov.b64 {%0, %1}, %2;" : "=f"(r.x), "=f"(r.y) : "l"(v));
    return r;
}

// ---------------------------------------------------------------------------
// zero / init
// ---------------------------------------------------------------------------
__global__ void zero_init(Scratch* s) {
    int idx = blockIdx.x * blockDim.x + threadIdx.x;
    int stride = gridDim.x * blockDim.x;
    for (int i = idx; i < NN; i += stride) s->deg[i] = 0;
    if (idx < (int)(NG * HID / 4)) ((float4*)s->pool)[idx] =
        make_float4(0.f, 0.f, 0.f, 0.f);
    if (idx < 2048) s->hist[idx] = 0;
    if (idx == 0) {
        s->st.prefix = 0;
        s->st.kk = KTOP;
        s->st.tie_count = 0;
    }
}

// ---------------------------------------------------------------------------
// CSR-by-destination build: count -> scan (warp-shuffle) -> fill (packed)
// ---------------------------------------------------------------------------
__global__ void count_deg(const int* __restrict__ col, int* __restrict__ deg) {
    int t = blockIdx.x * 256 + threadIdx.x;
    int e0 = t * 4;
    if (e0 >= EE) return;
    int4 c = *(const int4*)&col[e0];
    atomicAdd(&deg[c.x], 1);
    atomicAdd(&deg[c.y], 1);
    atomicAdd(&deg[c.z], 1);
    atomicAdd(&deg[c.w], 1);
}

__global__ void scan_deg(const int* __restrict__ deg, int* __restrict__ off,
                         int* __restrict__ cursor) {
    __shared__ int wsum[32];
    __shared__ int carry_s;
    int tid = threadIdx.x;               // 1024 threads
    int lane = tid & 31, wid = tid >> 5;
    if (tid == 0) carry_s = 0;
    __syncthreads();
    for (int base = 0; base < NN; base += 1024) {
        int i = base + tid;
        int v = (i < NN) ? deg[i] : 0;
        int x = v;
#pragma unroll
        for (int o = 1; o < 32; o <<= 1) {
            int t = __shfl_up_sync(0xFFFFFFFFu, x, o);
            if (lane >= o) x += t;
        }
        if (lane == 31) wsum[wid] = x;
        __syncthreads();
        if (wid == 0) {
            int w = wsum[lane];
#pragma unroll
            for (int o = 1; o < 32; o <<= 1) {
                int t = __shfl_up_sync(0xFFFFFFFFu, w, o);
                if (lane >= o) w += t;
            }
            wsum[lane] = w;
        }
        __syncthreads();
        int excl = x - v + (wid > 0 ? wsum[wid - 1] : 0) + carry_s;
        if (i < NN) { off[i] = excl; cursor[i] = excl; }
        __syncthreads();
        if (tid == 1023) carry_s = excl + v;
        __syncthreads();
    }
    if (tid == 0) off[NN] = carry_s;
}

__global__ void fill_eid(const int* __restrict__ row, const int* __restrict__ col,
                         int* __restrict__ cursor, int2* __restrict__ pack) {
    int t = blockIdx.x * 256 + threadIdx.x;
    int e0 = t * 4;
    if (e0 >= EE) return;
    int4 c = *(const int4*)&col[e0];
    int4 r = *(const int4*)&row[e0];
    int p0 = atomicAdd(&cursor[c.x], 1);
    int p1 = atomicAdd(&cursor[c.y], 1);
    int p2 = atomicAdd(&cursor[c.z], 1);
    int p3 = atomicAdd(&cursor[c.w], 1);
    pack[p0] = make_int2(e0 + 0, r.x);
    pack[p1] = make_int2(e0 + 1, r.y);
    pack[p2] = make_int2(e0 + 2, r.z);
    pack[p3] = make_int2(e0 + 3, r.w);
}

// ---------------------------------------------------------------------------
// GEMM: C[M x 128] = epilogue( (A + optional 2*H)[M x K] @ W[K x 128] + bias )
// Block tile 64 x 128, BK=16, 128 threads, 8x8 microtile, FFMA2 inner product.
// ---------------------------------------------------------------------------
struct GArgs {
    const float* A;
    const float* W;
    const float* bias;
    float* C;
};

template<int K, bool ADD2H, bool RELU>
__global__ __launch_bounds__(128, 4)
void gemm64(GArgs g0, GArgs g1, const float* __restrict__ Hh, int M)
{
    __shared__ __align__(16) float As[2][16][64];
    __shared__ __align__(16) float Bs[2][16][128];

    GArgs g = (blockIdx.y == 1) ? g1 : g0;
    const float* __restrict__ A = g.A;
    const float* __restrict__ W = g.W;

    const int m0 = blockIdx.x * 64;
    const int t  = threadIdx.x;
    const int tx = t & 15;
    const int ty = t >> 4;

    const int ar0 = t >> 2;
    const int akc = (t & 3) * 4;
    const int bkr = t >> 5;
    const int bc4 = (t & 31) * 4;

    unsigned long long acc2[8][4];
#pragma unroll
    for (int i = 0; i < 8; i++)
#pragma unroll
        for (int j = 0; j < 4; j++) acc2[i][j] = 0ull;

    float4 av[2], bv[4];

    auto ldg_tiles = [&](int k0) {
#pragma unroll
        for (int l = 0; l < 2; l++) {
            int m = m0 + ar0 + l * 32;
            float4 v = make_float4(0.f, 0.f, 0.f, 0.f);
            if (m < M) {
                v = *(const float4*)&A[(size_t)m * K + k0 + akc];
                if (ADD2H) {
                    float4 hv = *(const float4*)&Hh[(size_t)m * K + k0 + akc];
                    v.x += 2.f * hv.x; v.y += 2.f * hv.y;
                    v.z += 2.f * hv.z; v.w += 2.f * hv.w;
                }
            }
            av[l] = v;
        }
#pragma unroll
        for (int l = 0; l < 4; l++)
            bv[l] = *(const float4*)&W[(size_t)(k0 + bkr + l * 4) * 128 + bc4];
    };

    auto sts_tiles = [&](int buf) {
#pragma unroll
        for (int l = 0; l < 2; l++) {
            int r = ar0 + l * 32;
            As[buf][akc + 0][r] = av[l].x;
            As[buf][akc + 1][r] = av[l].y;
            As[buf][akc + 2][r] = av[l].z;
            As[buf][akc + 3][r] = av[l].w;
        }
#pragma unroll
        for (int l = 0; l < 4; l++)
            *(float4*)&Bs[buf][bkr + l * 4][bc4] = bv[l];
    };

    auto compute = [&](int buf) {
#pragma unroll
        for (int kk = 0; kk < 16; kk++) {
            float4 a0 = *(const float4*)&As[buf][kk][ty * 4];
            float4 a1 = *(const float4*)&As[buf][kk][32 + ty * 4];
            ulonglong2 p0 = *(const ulonglong2*)&Bs[buf][kk][tx * 4];
            ulonglong2 p1 = *(const ulonglong2*)&Bs[buf][kk][64 + tx * 4];
            unsigned long long bb[4] = {p0.x, p0.y, p1.x, p1.y};
            float aa[8] = {a0.x, a0.y, a0.z, a0.w, a1.x, a1.y, a1.z, a1.w};
#pragma unroll
            for (int i = 0; i < 8; i++) {
                unsigned long long ad = dup2(aa[i]);
                ffma2(acc2[i][0], ad, bb[0]);
                ffma2(acc2[i][1], ad, bb[1]);
                ffma2(acc2[i][2], ad, bb[2]);
                ffma2(acc2[i][3], ad, bb[3]);
            }
        }
    };

    ldg_tiles(0);
    sts_tiles(0);
    __syncthreads();
    int buf = 0;
    for (int k0 = 16; k0 < K; k0 += 16) {
        ldg_tiles(k0);
        compute(buf);
        sts_tiles(buf ^ 1);
        __syncthreads();
        buf ^= 1;
    }
    compute(buf);

    const float4 bias0 = *(const float4*)&g.bias[tx * 4];
    const float4 bias1 = *(const float4*)&g.bias[64 + tx * 4];
#pragma unroll
    for (int gi = 0; gi < 2; gi++) {
#pragma unroll
        for (int i = 0; i < 4; i++) {
            int m = m0 + gi * 32 + ty * 4 + i;
            if (m >= M) continue;
            int ri = gi * 4 + i;
            float2 c0 = unpk(acc2[ri][0]);
            float2 c1 = unpk(acc2[ri][1]);
            float2 c2 = unpk(acc2[ri][2]);
            float2 c3 = unpk(acc2[ri][3]);
            float4 v0, v1;
            v0.x = c0.x + bias0.x; v0.y = c0.y + bias0.y;
            v0.z = c1.x + bias0.z; v0.w = c1.y + bias0.w;
            v1.x = c2.x + bias1.x; v1.y = c2.y + bias1.y;
            v1.z = c3.x + bias1.z; v1.w = c3.y + bias1.w;
            if (RELU) {
                v0.x = fmaxf(v0.x, 0.f); v0.y = fmaxf(v0.y, 0.f);
                v0.z = fmaxf(v0.z, 0.f); v0.w = fmaxf(v0.w, 0.f);
                v1.x = fmaxf(v1.x, 0.f); v1.y = fmaxf(v1.y, 0.f);
                v1.z = fmaxf(v1.z, 0.f); v1.w = fmaxf(v1.w, 0.f);
            }
            *(float4*)&g.C[(size_t)m * 128 + tx * 4] = v0;
            *(float4*)&g.C[(size_t)m * 128 + 64 + tx * 4] = v1;
        }
    }
}

// ---------------------------------------------------------------------------
// gather (weight 1): Ai[n] = sum over incoming edges of h[src]
// ---------------------------------------------------------------------------
__global__ void gather_ones(const int* __restrict__ off, const int2* __restrict__ pack,
                            const float* __restrict__ h, float* __restrict__ Ai)
{
    int n = blockIdx.x * 8 + (threadIdx.x >> 5);
    if (n >= NN) return;
    int lane = threadIdx.x & 31;
    int s0 = __ldg(&off[n]);
    int cnt = __ldg(&off[n + 1]) - s0;
    float4 acc0 = make_float4(0.f, 0.f, 0.f, 0.f);
    float4 acc1 = make_float4(0.f, 0.f, 0.f, 0.f);
    for (int base = 0; base < cnt; base += 32) {
        int m = cnt - base; if (m > 32) m = 32;
        int src = 0;
        if (base + lane < cnt) src = __ldg(&pack[s0 + base + lane].y);
        int j = 0;
        for (; j + 2 <= m; j += 2) {
            int r0 = __shfl_sync(0xFFFFFFFFu, src, j);
            int r1 = __shfl_sync(0xFFFFFFFFu, src, j + 1);
            float4 v0 = *(const float4*)(h + (size_t)r0 * HID + lane * 4);
            float4 v1 = *(const float4*)(h + (size_t)r1 * HID + lane * 4);
            acc0.x += v0.x; acc0.y += v0.y; acc0.z += v0.z; acc0.w += v0.w;
            acc1.x += v1.x; acc1.y += v1.y; acc1.z += v1.z; acc1.w += v1.w;
        }
        if (j < m) {
            int r0 = __shfl_sync(0xFFFFFFFFu, src, j);
            float4 v0 = *(const float4*)(h + (size_t)r0 * HID + lane * 4);
            acc0.x += v0.x; acc0.y += v0.y; acc0.z += v0.z; acc0.w += v0.w;
        }
    }
    float4 acc = make_float4(acc0.x + acc1.x, acc0.y + acc1.y,
                             acc0.z + acc1.z, acc0.w + acc1.w);
    *(float4*)(Ai + (size_t)n * HID + lane * 4) = acc;
}

// ---------------------------------------------------------------------------
// per-edge dot: ew[e] = <X[row], X[col]> — 4 edges per warp
// ---------------------------------------------------------------------------
__global__ void ew_kernel(const int* __restrict__ row, const int* __restrict__ col,
                          const float* __restrict__ X, float* __restrict__ ew)
{
    int gw = blockIdx.x * 8 + (threadIdx.x >> 5);
    int e0 = gw * 4;
    if (e0 >= EE) return;
    int lane = threadIdx.x & 31;
    int r[4], c[4];
#pragma unroll
    for (int q = 0; q < 4; q++) {
        r[q] = __ldg(&row[e0 + q]);
        c[q] = __ldg(&col[e0 + q]);
    }
    float s[4];
#pragma unroll
    for (int q = 0; q < 4; q++) {
        float4 a = *(const float4*)(X + (size_t)r[q] * HID + lane * 4);
        float4 b = *(const float4*)(X + (size_t)c[q] * HID + lane * 4);
        s[q] = a.x * b.x + a.y * b.y + a.z * b.z + a.w * b.w;
    }
#pragma unroll
    for (int off = 16; off >= 1; off >>= 1) {
#pragma unroll
        for (int q = 0; q < 4; q++)
            s[q] += __shfl_xor_sync(0xFFFFFFFFu, s[q], off);
    }
    if (lane == 0)
        *(float4*)&ew[e0] = make_float4(s[0], s[1], s[2], s[3]);
}

// ---------------------------------------------------------------------------
// radix-select histogram passes (shared-memory privatized, float4 loads)
// ---------------------------------------------------------------------------
__global__ void hist_kernel(const float* __restrict__ ew, unsigned* __restrict__ hist,
                            const SelState* __restrict__ st, int pass)
{
    __shared__ unsigned sh[2048];
    for (int i = threadIdx.x; i < 2048; i += blockDim.x) sh[i] = 0;
    __syncthreads();
    unsigned pref = st->prefix;
    int stride = gridDim.x * blockDim.x;
    for (int i = blockIdx.x * blockDim.x + threadIdx.x; i < EE / 4; i += stride) {
        float4 w = *(const float4*)&ew[i * 4];
        unsigned u[4] = {fkey(w.x), fkey(w.y), fkey(w.z), fkey(w.w)};
#pragma unroll
        for (int q = 0; q < 4; q++) {
            if (pass == 1) {
                if ((u[q] >> 21) == pref) atomicAdd(&sh[(u[q] >> 10) & 2047u], 1u);
            } else {
                if ((u[q] >> 10) == pref) atomicAdd(&sh[u[q] & 1023u], 1u);
            }
        }
    }
    __syncthreads();
    for (int i = threadIdx.x; i < 2048; i += blockDim.x)
        if (sh[i]) atomicAdd(&hist[i], sh[i]);
}

// pass 0 variant (no predicate)
__global__ void hist0_kernel(const float* __restrict__ ew, unsigned* __restrict__ hist)
{
    __shared__ unsigned sh[2048];
    for (int i = threadIdx.x; i < 2048; i += blockDim.x) sh[i] = 0;
    __syncthreads();
    int stride = gridDim.x * blockDim.x;
    for (int i = blockIdx.x * blockDim.x + threadIdx.x; i < EE / 4; i += stride) {
        float4 w = *(const float4*)&ew[i * 4];
        atomicAdd(&sh[fkey(w.x) >> 21], 1u);
        atomicAdd(&sh[fkey(w.y) >> 21], 1u);
        atomicAdd(&sh[fkey(w.z) >> 21], 1u);
        atomicAdd(&sh[fkey(w.w) >> 21], 1u);
    }
    __syncthreads();
    for (int i = threadIdx.x; i < 2048; i += blockDim.x)
        if (sh[i]) atomicAdd(&hist[i], sh[i]);
}

// ---------------------------------------------------------------------------
// suffix-scan of histogram; pick bucket, update state; zeroes hist for next use
// ---------------------------------------------------------------------------
__global__ void scan_kernel(unsigned* __restrict__ hist, SelState* __restrict__ st,
                            int nbins, int bits, int last)
{
    __shared__ unsigned a[2048], b[2048];
    __shared__ int bstar;
    int tid = threadIdx.x;
    for (int i = tid; i < 2048; i += blockDim.x) {
        a[i] = (i < nbins) ? hist[i] : 0u;
        hist[i] = 0u;
    }
    __syncthreads();
    unsigned* src = a;
    unsigned* dst = b;
    for (int off = 1; off < nbins; off <<= 1) {
        for (int i = tid; i < nbins; i += blockDim.x)
            dst[i] = src[i] + ((i + off < nbins) ? src[i + off] : 0u);
        __syncthreads();
        unsigned* t = src; src = dst; dst = t;
    }
    int kk = st->kk;
    for (int i = tid; i < nbins; i += blockDim.x) {
        unsigned Si = src[i];
        unsigned Sn = (i + 1 < nbins) ? src[i + 1] : 0u;
        if (Si >= (unsigned)kk && Sn < (unsigned)kk) bstar = i;
    }
    __syncthreads();
    if (tid == 0) {
        int bs = bstar;
        unsigned greater = (bs + 1 < nbins) ? src[bs + 1] : 0u;
        st->kk = kk - (int)greater;
        st->prefix = (st->prefix << bits) | (unsigned)bs;
        if (last) {
            st->threshold = st->prefix;
            st->needed = st->kk;
        }
    }
}

// ---------------------------------------------------------------------------
// weighted gather with inline classification (one warp per node, no fp atomics)
// ---------------------------------------------------------------------------
__global__ void gather_sel(const int* __restrict__ off, const int2* __restrict__ pack,
                           const float* __restrict__ h, const float* __restrict__ ew,
                           float* __restrict__ At, float* __restrict__ Ar,
                           int* __restrict__ tie, SelState* __restrict__ st)
{
    int n = blockIdx.x * 8 + (threadIdx.x >> 5);
    if (n >= NN) return;
    int lane = threadIdx.x & 31;
    unsigned T = st->threshold;
    int s0 = __ldg(&off[n]);
    int cnt = __ldg(&off[n + 1]) - s0;
    float4 at0 = make_float4(0.f, 0.f, 0.f, 0.f);
    float4 at1 = make_float4(0.f, 0.f, 0.f, 0.f);
    float4 ar0 = make_float4(0.f, 0.f, 0.f, 0.f);
    float4 ar1 = make_float4(0.f, 0.f, 0.f, 0.f);
    for (int base = 0; base < cnt; base += 32) {
        int m = cnt - base; if (m > 32) m = 32;
        int src = 0; float w = 0.f; unsigned u = 0;
        if (base + lane < cnt) {
            int2 pk = __ldg(&pack[s0 + base + lane]);
            src = pk.y;
            w = __ldg(&ew[pk.x]);
            u = fkey(w);
            if (u == T) {
                int q = atomicAdd(&st->tie_count, 1);
                if (q < MAX_TIES) tie[q] = pk.x;
            }
        }
        for (int j = 0; j < m; j++) {
            unsigned uj = __shfl_sync(0xFFFFFFFFu, u, j);
            if (uj == T) continue;
            int rj = __shfl_sync(0xFFFFFFFFu, src, j);
            float wj = __shfl_sync(0xFFFFFFFFu, w, j);
            float4 v = *(const float4*)(h + (size_t)rj * HID + lane * 4);
            v.x *= wj; v.y *= wj; v.z *= wj; v.w *= wj;
            if (uj > T) {
                if (j & 1) {
                    at1.x += v.x; at1.y += v.y; at1.z += v.z; at1.w += v.w;
                } else {
                    at0.x += v.x; at0.y += v.y; at0.z += v.z; at0.w += v.w;
                }
            } else {
                if (j & 1) {
                    ar1.x += v.x; ar1.y += v.y; ar1.z += v.z; ar1.w += v.w;
                } else {
                    ar0.x += v.x; ar0.y += v.y; ar0.z += v.z; ar0.w += v.w;
                }
            }
        }
    }
    float4 at = make_float4(at0.x + at1.x, at0.y + at1.y,
                            at0.z + at1.z, at0.w + at1.w);
    float4 ar = make_float4(ar0.x + ar1.x, ar0.y + ar1.y,
                            ar0.z + ar1.z, ar0.w + ar1.w);
    *(float4*)(At + (size_t)n * HID + lane * 4) = at;
    *(float4*)(Ar + (size_t)n * HID + lane * 4) = ar;
}

// ---------------------------------------------------------------------------
// tie resolution + tie scatter (RED onto fully-written At/Ar)
// ---------------------------------------------------------------------------
__global__ void tie_resolve(const int* __restrict__ row, const int* __restrict__ col,
                            const float* __restrict__ h, const float* __restrict__ ew,
                            int* __restrict__ tie, float* __restrict__ At,
                            float* __restrict__ Ar, const SelState* __restrict__ st)
{
    __shared__ int s[MAX_TIES];
    int C = st->tie_count;
    if (C > MAX_TIES) C = MAX_TIES;
    int nd = st->needed;
    int tid = threadIdx.x;

    for (int i = tid; i < C; i += blockDim.x) s[i] = tie[i];
    __syncthreads();
    if (C > nd) {
        for (int ph = 0; ph < C; ph++) {
            for (int i = 2 * tid + (ph & 1); i + 1 < C; i += 2 * blockDim.x) {
                if (s[i] > s[i + 1]) { int t = s[i]; s[i] = s[i + 1]; s[i + 1] = t; }
            }
            __syncthreads();
        }
    }
    int lane = tid & 31;
    for (int j = tid >> 5; j < C; j += blockDim.x >> 5) {
        int e = s[j];
        float w = __ldg(&ew[e]);
        int r = __ldg(&row[e]);
        int c = __ldg(&col[e]);
        float4 v = *(const float4*)(h + (size_t)r * HID + lane * 4);
        v.x *= w; v.y *= w; v.z *= w; v.w *= w;
        float* dst = (C <= nd || j < nd) ? At : Ar;
        red4(dst + (size_t)c * HID + lane * 4, v);
    }
}

// ---------------------------------------------------------------------------
// pooling: pooled[batch[n]] += x1[n] + x2[n]   (batch sorted -> run flush)
// NPB=64: shorter serial dependent-add chain per block
// ---------------------------------------------------------------------------
#define NPB 64
__global__ void pool_kernel(const float* __restrict__ x1, const float* __restrict__ x2,
                            const int* __restrict__ batch, float* __restrict__ pooled)
{
    int f = threadIdx.x;
    int n0 = blockIdx.x * NPB;
    if (n0 >= NN) return;
    int n1 = n0 + NPB;
    if (n1 > NN) n1 = NN;
    int cur = batch[n0];
    float acc = 0.f;
    for (int n = n0; n < n1; n++) {
        int b = batch[n];
        if (b != cur) {
            atomicAdd(&pooled[cur * HID + f], acc);
            acc = 0.f;
            cur = b;
        }
        acc += x1[(size_t)n * HID + f] + x2[(size_t)n * HID + f];
    }
    atomicAdd(&pooled[cur * HID + f], acc);
}

// ---------------------------------------------------------------------------
// head: p = relu(pooled@post_W+post_b); logits = p@ro_W+ro_b; log_softmax
// ---------------------------------------------------------------------------
__global__ void head_kernel(const float* __restrict__ pool,
                            const float* __restrict__ pW, const float* __restrict__ pb,
                            const float* __restrict__ rW, const float* __restrict__ rb,
                            float* __restrict__ out)
{
    __shared__ float rowv[HID], p[HID], lg[NCLS];
    int g = blockIdx.x, t = threadIdx.x;
    rowv[t] = pool[g * HID + t];
    __syncthreads();
    float s = pb[t];
#pragma unroll 8
    for (int k = 0; k < HID; k++) s += rowv[k] * pW[k * HID + t];
    p[t] = fmaxf(s, 0.f);
    __syncthreads();
    if (t < NCLS) {
        float s2 = rb[t];
#pragma unroll 8
        for (int k = 0; k < HID; k++) s2 += p[k] * rW[k * NCLS + t];
        lg[t] = s2;
    }
    __syncthreads();
    if (t == 0) {
        float mx = lg[0];
        for (int j = 1; j < NCLS; j++) mx = fmaxf(mx, lg[j]);
        float se = 0.f;
        for (int j = 0; j < NCLS; j++) se += expf(lg[j] - mx);
        float l = logf(se) + mx;
        for (int j = 0; j < NCLS; j++) out[g * NCLS + j] = lg[j] - l;
    }
}

// ---------------------------------------------------------------------------
// launch
// ---------------------------------------------------------------------------
extern "C" void kernel_launch(void* const* d_in, const int* in_sizes, int n_in,
                              void* d_out, int out_size)
{
    (void)in_sizes; (void)n_in; (void)out_size;
    const float* x     = (const float*)d_in[0];
    const int*   ei    = (const int*)d_in[1];
    const int*   row   = ei;
    const int*   col   = ei + EE;
    const int*   batch = (const int*)d_in[2];
    const float* preW  = (const float*)d_in[3];
    const float* preB  = (const float*)d_in[4];
    const int LW = 2 * HID * HID, LB = 2 * HID;   // last layer (index 2)
    const float* c1W1 = (const float*)d_in[5]  + LW;
    const float* c1b1 = (const float*)d_in[6]  + LB;
    const float* c1W2 = (const float*)d_in[7]  + LW;
    const float* c1b2 = (const float*)d_in[8]  + LB;
    const float* c3W1 = (const float*)d_in[9]  + LW;
    const float* c3b1 = (const float*)d_in[10] + LB;
    const float* c3W2 = (const float*)d_in[11] + LW;
    const float* c3b2 = (const float*)d_in[12] + LB;
    const float* c4W1 = (const float*)d_in[13] + LW;
    const float* c4b1 = (const float*)d_in[14] + LB;
    const float* c4W2 = (const float*)d_in[15] + LW;
    const float* c4b2 = (const float*)d_in[16] + LB;
    const float* postW = (const float*)d_in[17];
    const float* postB = (const float*)d_in[18];
    const float* roW   = (const float*)d_in[19];
    const float* roB   = (const float*)d_in[20];
    float* out = (float*)d_out;

    Scratch* s = nullptr;
    cudaGetSymbolAddress((void**)&s, g_s);

    const int GB = (NN + 63) / 64;           // gemm blocks (x)
    const int NB = (NN + 7) / 8;             // node-warp blocks
    const int WB = (EE / 4 + 7) / 8;         // ew warp blocks (4 edges/warp)
    const int QB = (EE / 4 + 255) / 256;     // quarter-edge thread blocks
    dim3 g1(GB, 1), g2(GB, 2);

    zero_init<<<256, 256>>>(s);

    // CSR-by-destination build (independent of h — run early)
    count_deg<<<QB, 256>>>(col, s->deg);
    scan_deg<<<1, 1024>>>(s->deg, s->off, s->cursor);
    fill_eid<<<QB, 256>>>(row, col, s->cursor, s->pack);

    // h = x @ pre_W + pre_b
    {
        GArgs a{x, preW, preB, s->h};
        gemm64<FIN, false, false><<<g1, 128>>>(a, a, nullptr, NN);
    }

    // invariance branch (only layer 2 matters)
    gather_ones<<<NB, 256>>>(s->off, s->pack, s->h, s->Ai);
    {
        GArgs a{s->Ai, c3W1, c3b1, s->T1};
        gemm64<HID, true, true><<<g1, 128>>>(a, a, s->h, NN);
    }
    {
        GArgs a{s->T1, c3W2, c3b2, s->X1};
        gemm64<HID, false, true><<<g1, 128>>>(a, a, nullptr, NN);
    }

    // per-edge weights (4 edges per warp)
    ew_kernel<<<WB, 256>>>(row, col, s->X1, s->ew);

    // exact top-k (k = 400000) radix select: 11 / 11 / 10 bits
    hist0_kernel<<<1024, 256>>>(s->ew, s->hist);
    scan_kernel<<<1, 1024>>>(s->hist, &s->st, 2048, 11, 0);
    hist_kernel<<<1024, 256>>>(s->ew, s->hist, &s->st, 1);
    scan_kernel<<<1, 1024>>>(s->hist, &s->st, 2048, 11, 0);
    hist_kernel<<<1024, 256>>>(s->ew, s->hist, &s->st, 2);
    scan_kernel<<<1, 1024>>>(s->hist, &s->st, 1024, 10, 1);

    // weighted gather with inline classification; ties deferred
    gather_sel<<<NB, 256>>>(s->off, s->pack, s->h, s->ew,
                            s->At, s->Ar, s->tie, &s->st);
    tie_resolve<<<1, 1024>>>(row, col, s->h, s->ew, s->tie, s->At, s->Ar, &s->st);

    // dual-branch layer 1: T1 = relu((At+2h)@c1W1+b), T2 = relu((Ar+2h)@c4W1+b)
    {
        GArgs a{s->At, c1W1, c1b1, s->T1};
        GArgs b{s->Ar, c4W1, c4b1, s->T2};
        gemm64<HID, true, true><<<g2, 128>>>(a, b, s->h, NN);
    }
    // dual-branch layer 2: X1 = relu(T1@c1W2+b), X2 = relu(T2@c4W2+b)
    {
        GArgs a{s->T1, c1W2, c1b2, s->X1};
        GArgs b{s->T2, c4W2, c4b2, s->X2};
        gemm64<HID, false, true><<<g2, 128>>>(a, b, nullptr, NN);
    }

    // pool + head
    pool_kernel<<<(NN + NPB - 1) / NPB, HID>>>(s->X1, s->X2, batch, s->pool);
    head_kernel<<<NG, HID>>>(s->pool, postW, postB, roW, roB, out);
}